// round 8
// baseline (speedup 1.0000x reference)
#include <cuda_runtime.h>
#include <cuda_bf16.h>

// GruDirection3d forward wavefront:
//   out[d,y,x] = z*h_tilde + (1-z)*out[d-1,y-1,x-1],  border -> h0
//
// R8: barrier-free warp-pipelined wavefront. Warp y owns row y of every
// plane. Dependency: warp y @ plane d needs only warp y-1 @ plane d-1
// (row y of the shifted ext tile). Sync = per-warp progress flags with
// acquire/release smem ops; NO __syncthreads in the main loop. 4-slot ring
// of 33x33 ext tiles (borders pinned h0); backpressure prog[y+1] >= d-2
// licenses slot reuse:
//   - producer-wait:  warp y reads slot (d-1)&3 row y, written by warp y-1
//     at plane d-1  -> wait prog[y-1] >= d.
//   - overwrite hazard: next writer of slot (d-1)&3 row y is warp y-1 at
//     plane d+3, which its own backpressure (prog[y] >= d+1) delays until
//     warp y finished plane d. QED.
// Warp 0 / row 0 / col 0 read the constant h0 border -> pipeline self-starts.

#define EXT   33
#define PLANE 1024
#define PD    4

__device__ __forceinline__ int ld_acq(const int* p) {
    int v;
    asm volatile("ld.acquire.cta.b32 %0, [%1];" : "=r"(v) : "l"(p) : "memory");
    return v;
}
__device__ __forceinline__ void st_rel(int* p, int v) {
    asm volatile("st.release.cta.b32 [%0], %1;" :: "l"(p), "r"(v) : "memory");
}

__global__ __launch_bounds__(1024, 2)
void gru3d_wf(const float* __restrict__ z,
              const float* __restrict__ ht,
              const float* __restrict__ h0p,
              float* __restrict__ out)
{
    __shared__ float buf[4][EXT * EXT];
    __shared__ int prog[32];

    const float h0 = __ldg(h0p);
    const int tid = threadIdx.x;
    const int y = tid >> 5;
    const int x = tid & 31;

    if (tid < 32) prog[tid] = 0;
    // Init only the h0 borders (row 0, col 0) of each slot; writers never
    // touch them (they write rows 1..32, cols 1..32).
    for (int i = tid; i < 4 * EXT; i += 1024) {
        const int s = i / EXT, c = i % EXT;
        buf[s][c] = h0;            // row 0
        buf[s][c * EXT] = h0;      // col 0
    }
    __syncthreads();   // the only block barrier

    const size_t base = (size_t)blockIdx.x * (32 * PLANE) + (size_t)(y * 32 + x);
    const float* zp = z  + base;
    const float* hp = ht + base;
    float*       op = out + base;

    // Depth-4 register prefetch: covers DRAM latency over ~4 pipeline links.
    float zb[PD], hb[PD];
    #pragma unroll
    for (int s = 0; s < PD; ++s) {
        zb[s] = zp[(size_t)s * PLANE];
        hb[s] = hp[(size_t)s * PLANE];
    }

    const int ridx = y * EXT + x;              // prev (y-1,x-1) in ext coords
    const int widx = (y + 1) * EXT + (x + 1);  // own output cell

    int* const pprev = (int*)&prog[y - 1];     // valid only when y>0
    int* const pnext = (int*)&prog[y + 1];     // valid only when y<31
    int* const pme   = (int*)&prog[y];

    #pragma unroll
    for (int d = 0; d < 32; ++d) {
        const int s = d & (PD - 1);
        const float zz = zb[s];
        const float hh = hb[s];
        if (d + PD < 32) {
            zb[s] = zp[(size_t)(d + PD) * PLANE];
            hb[s] = hp[(size_t)(d + PD) * PLANE];
        }

        float pv;
        if (d == 0) {
            pv = h0;                            // plane -1 is the h0 border
        } else {
            if (y > 0) {
                while (ld_acq(pprev) < d) { }   // warp y-1 done plane d-1
            }
            pv = buf[(d - 1) & 3][ridx];        // row 0 / col 0 read h0
        }

        const float o = fmaf(zz, hh - pv, pv);  // z*ht + (1-z)*prev

        if (y < 31) {                           // row 32 is never read
            if (d >= 4) {
                while (ld_acq(pnext) < d - 2) { }   // slot-reuse license
            }
            buf[d & 3][widx] = o;
        }
        __syncwarp();                           // all lanes' STS before flag
        st_rel(pme, d + 1);
        op[(size_t)d * PLANE] = o;
    }
}

extern "C" void kernel_launch(void* const* d_in, const int* in_sizes, int n_in,
                              void* d_out, int out_size)
{
    const float* z  = (const float*)d_in[0];
    const float* ht = (const float*)d_in[1];
    const float* h0 = (const float*)d_in[2];
    float* out = (float*)d_out;

    const int n_volumes = out_size / (32 * PLANE);   // B*C = 192
    gru3d_wf<<<n_volumes, 1024>>>(z, ht, h0, out);
}

// round 10
// speedup vs baseline: 1.6911x; 1.6911x over previous
#include <cuda_runtime.h>
#include <cuda_bf16.h>
#include <cstdint>

// GruDirection3d forward wavefront:
//   out[d,y,x] = z*h_tilde + (1-z)*out[d-1,y-1,x-1],  border -> h0
//
// R10 (= R9 + build fix): LSU-op-minimized plane sweep. 256 threads/CTA;
// thread (y=tid>>3, x4=tid&7) owns float4 x=4*x4..4*x4+3 of row y. Warp = 4
// consecutive rows (coalesced). The (y-1,x-1) shifted dependency resolves in
// REGISTERS:
//   p1..p3 = shfl_up(o.{x,y,z}, 8)   (row y-1, same group)
//   p0     = shfl_up(o.w, 9)          (row y-1, group x4-1, .w)
// Warp-boundary rows (y%4==0) read one float4 from a 2x8x8 smem exchange
// written by rows y%4==3. z/h_tilde stream through a 5-slot cp.async ring
// (4 planes in flight, 32KB outstanding/SM). Each thread owns its ring
// element exclusively -> ring reuse needs no barrier; ONE __syncthreads per
// plane (for the 2KB exchange only).

#define D_PF   4
#define RING   5
#define PLANE4 256     // float4 per plane

__device__ __forceinline__ void cpa16(unsigned int s, const void* g) {
    asm volatile("cp.async.cg.shared.global [%0], [%1], 16;" :: "r"(s), "l"(g));
}
__device__ __forceinline__ void cpa_commit() {
    asm volatile("cp.async.commit_group;" ::: "memory");
}
__device__ __forceinline__ void cpa_wait() {
    asm volatile("cp.async.wait_group %0;" :: "n"(D_PF) : "memory");
}

__global__ __launch_bounds__(256)
void gru3d_kernel(const float4* __restrict__ z,
                  const float4* __restrict__ ht,
                  const float*  __restrict__ h0p,
                  float4*       __restrict__ out)
{
    __shared__ float4 rz[RING][PLANE4];    // 20KB
    __shared__ float4 rh[RING][PLANE4];    // 20KB
    __shared__ float4 sb[2][8][8];         // 2KB row exchange

    const float h0 = __ldg(h0p);
    const int tid  = threadIdx.x;
    const int lane = tid & 31;
    const int w    = tid >> 5;     // warp id == y>>2
    const int x4   = tid & 7;
    const int y    = tid >> 3;

    const size_t vb = (size_t)blockIdx.x * (32 * PLANE4) + (size_t)tid;
    const float4* zp = z  + vb;
    const float4* hp = ht + vb;
    float4*       op = out + vb;

    const unsigned int rz_a = (unsigned int)__cvta_generic_to_shared(&rz[0][tid]);
    const unsigned int rh_a = (unsigned int)__cvta_generic_to_shared(&rh[0][tid]);
    const unsigned int SS = PLANE4 * sizeof(float4);   // ring slot stride (bytes)

    // Prologue: planes 0..D_PF-1 in flight (one commit group per plane).
    #pragma unroll
    for (int s = 0; s < D_PF; ++s) {
        cpa16(rz_a + s * SS, zp + (size_t)s * PLANE4);
        cpa16(rh_a + s * SS, hp + (size_t)s * PLANE4);
        cpa_commit();
    }

    const int rcl = (w > 0) ? (w - 1) : 0;   // exchange row to read (clamped)
    float4 o = make_float4(0.f, 0.f, 0.f, 0.f);   // prev-plane output (d==0 unused)

    #pragma unroll
    for (int d = 0; d < 32; ++d) {
        // One commit group per iteration (empty groups in the tail keep the
        // wait_group(D_PF) accounting uniform -> plane d's group complete).
        if (d + D_PF < 32) {
            const int sl = (d + D_PF) % RING;   // == (d-1)%RING: my element,
            cpa16(rz_a + sl * SS, zp + (size_t)(d + D_PF) * PLANE4); // consumed
            cpa16(rh_a + sl * SS, hp + (size_t)(d + D_PF) * PLANE4); // by me at
        }                                                            // d-1.
        cpa_commit();
        cpa_wait();            // plane d resident in my ring elements
        __syncthreads();       // sb writes of plane d-1 visible

        const int cs = d % RING;
        const float4 zd = rz[cs][tid];
        const float4 hd = rh[cs][tid];

        // Shifted prev-plane values (register path).
        const float ux = __shfl_up_sync(0xffffffffu, o.x, 8);
        const float uy = __shfl_up_sync(0xffffffffu, o.y, 8);
        const float uz = __shfl_up_sync(0xffffffffu, o.z, 8);
        const float b9 = __shfl_up_sync(0xffffffffu, o.w, 9);
        // Warp-boundary path: row y-1 is previous warp's last row, in sb.
        const float4 sv  = sb[(d + 1) & 1][rcl][x4];        // broadcast read
        const float  sbw = __shfl_up_sync(0xffffffffu, sv.w, 1);

        const bool frow = (lane < 8);    // y%4==0: use smem path
        float p0 = frow ? sbw  : b9;
        float p1 = frow ? sv.x : ux;
        float p2 = frow ? sv.y : uy;
        float p3 = frow ? sv.z : uz;
        if (x4 == 0) p0 = h0;                        // x-1 < 0 border
        if (y == 0 || d == 0) { p0 = h0; p1 = h0; p2 = h0; p3 = h0; }

        o.x = fmaf(zd.x, hd.x - p0, p0);
        o.y = fmaf(zd.y, hd.y - p1, p1);
        o.z = fmaf(zd.z, hd.z - p2, p2);
        o.w = fmaf(zd.w, hd.w - p3, p3);

        op[(size_t)d * PLANE4] = o;
        if (lane >= 24) sb[d & 1][w][x4] = o;   // rows y%4==3 -> exchange
    }
}

extern "C" void kernel_launch(void* const* d_in, const int* in_sizes, int n_in,
                              void* d_out, int out_size)
{
    const float4* z  = (const float4*)d_in[0];
    const float4* ht = (const float4*)d_in[1];
    const float*  h0 = (const float*)d_in[2];
    float4* out = (float4*)d_out;

    const int n_volumes = out_size / (32 * PLANE4 * 4);   // B*C = 192
    gru3d_kernel<<<n_volumes, 256>>>(z, ht, h0, out);
}

// round 11
// speedup vs baseline: 1.9673x; 1.1633x over previous
#include <cuda_runtime.h>
#include <cuda_bf16.h>
#include <cstdint>

// GruDirection3d forward wavefront:
//   out[d,y,x] = z*h_tilde + (1-z)*out[d-1,y-1,x-1],  border -> h0
//
// R11: 512-thread CTAs, TWO volumes per CTA as independent 256-thread
// domains synced by named barriers (bar.sync 1/2). Each domain: float4
// plane sweep with the R2-style 33-stride smem ext tile (shifted scalar
// LDS/STS are bank permutations -> conflict-free), register prefetch
// depth 4. Rationale: per-plane period is LSU-issue + barrier bound;
// float4 cuts warp LSU ops 4x vs R6 while 16 warps/SM in two decoupled
// barrier domains cover each other's drain/latency (R10's 8 warps could
// not). Grid = 96 CTAs -> perfect single wave, no timeshare tail.

#define PLANE4 256      // float4 per 32x32 plane
#define STRIDE 33
#define TILE   (STRIDE * 33)
#define PD     4

__global__ __launch_bounds__(512, 1)
void gru3d_kernel(const float4* __restrict__ zv,
                  const float4* __restrict__ hv,
                  const float*  __restrict__ h0p,
                  float4*       __restrict__ ov)
{
    __shared__ float buf[2][2][TILE];   // [domain][phase][tile] = 17.4KB

    const float h0 = __ldg(h0p);
    const int tid = threadIdx.x;
    const int dom = tid >> 8;           // 0 or 1: which volume
    const int t   = tid & 255;

    // Init all tiles to h0 (interior overwritten; border row/col stay h0).
    #pragma unroll
    for (int i = tid; i < 2 * 2 * TILE; i += 512)
        (&buf[0][0][0])[i] = h0;

    const int y  = t >> 3;    // 0..31
    const int x4 = t & 7;     // 0..7

    const int vol = blockIdx.x * 2 + dom;
    const size_t base = (size_t)vol * (32 * PLANE4) + (size_t)(y * 8 + x4);
    const float4* zp = zv + base;
    const float4* hp = hv + base;
    float4*       op = ov + base;

    // Register prefetch: planes 0..PD-1 in flight.
    float4 zb[PD], hb[PD];
    #pragma unroll
    for (int s = 0; s < PD; ++s) {
        zb[s] = zp[(size_t)s * PLANE4];
        hb[s] = hp[(size_t)s * PLANE4];
    }

    __syncthreads();   // tile init visible to both domains

    // ext[r][c] == prev_out[r-1][c-1]; read ext[y][4x4+j], write ext[y+1][4x4+1+j].
    const int rbase = y * STRIDE + 4 * x4;
    const int wbase = (y + 1) * STRIDE + 4 * x4 + 1;
    const int bid = 1 + dom;            // named barrier id per domain

    #pragma unroll
    for (int d = 0; d < 32; ++d) {
        const int s = d & (PD - 1);
        const float4 zc = zb[s];
        const float4 hc = hb[s];

        if (d + PD < 32) {
            zb[s] = zp[(size_t)(d + PD) * PLANE4];
            hb[s] = hp[(size_t)(d + PD) * PLANE4];
        }

        const float* rb = &buf[dom][(d + 1) & 1][rbase];
        const float p0 = rb[0], p1 = rb[1], p2 = rb[2], p3 = rb[3];

        float4 o;
        o.x = fmaf(zc.x, hc.x - p0, p0);
        o.y = fmaf(zc.y, hc.y - p1, p1);
        o.z = fmaf(zc.z, hc.z - p2, p2);
        o.w = fmaf(zc.w, hc.w - p3, p3);

        float* wb = &buf[dom][d & 1][wbase];
        wb[0] = o.x; wb[1] = o.y; wb[2] = o.z; wb[3] = o.w;

        op[(size_t)d * PLANE4] = o;

        // Domain-local barrier: 256 threads, ids 1/2. Decoupled domains.
        asm volatile("bar.sync %0, 256;" :: "r"(bid) : "memory");
    }
}

extern "C" void kernel_launch(void* const* d_in, const int* in_sizes, int n_in,
                              void* d_out, int out_size)
{
    const float4* z  = (const float4*)d_in[0];
    const float4* ht = (const float4*)d_in[1];
    const float*  h0 = (const float*)d_in[2];
    float4* out = (float4*)d_out;

    const int n_volumes = out_size / (32 * PLANE4 * 4);   // B*C = 192
    gru3d_kernel<<<n_volumes / 2, 512>>>(z, ht, h0, out);
}